// round 13
// baseline (speedup 1.0000x reference)
#include <cuda_runtime.h>

// GPUBiasingMultiModel R13: R10 structure (TILE=1024, 128 thr, 2x float4 per
// thread) with the patch scan HOISTED out of the store loop.
//
//  - Phase A  : compact chunk hyps of model m; walk <=4-hop backoff chain.
//  - Phase A' : per (hyp, level) binary search for in-tile arcs -> per-(hyp,
//               owning-warp) smem buckets (values pre-scaled, key=level<<6|j).
//  - Phase A'': each thread scans its warp's buckets ONCE and extracts the
//               patches targeting its register slots into thread-local arrays,
//               deduped by min key (= exact reference priority), grouped by
//               hyp slot ascending.
//  - Store    : per hyp: 8 fma + ONE register compare (i == next_slot) +
//               4x STG.128 __stcs. Patch applies are rare local-array walks.
//  - Overflow (>NCAP hyps, bucket >BCAP, >PCAP per thread) -> correct
//    post-store slow pass (full-priority gmem patch), ordered by a barrier.

#define MAXLVL 4
#define TILE   1024   // labels per tile (8 floats/thread @128 thr)
#define CHUNK  128    // hyp indices per block (== blockDim)
#define NCAP   32     // hyp slots with fast-path buckets
#define BCAP   8      // entries per (hyp, warp) bucket
#define PCAP   8      // per-thread register patch capacity

__device__ __forceinline__ void setc(float4& v, int c, float x) {
    v.x = (c == 0) ? x : v.x;
    v.y = (c == 1) ? x : v.y;
    v.z = (c == 2) ? x : v.z;
    v.w = (c == 3) ? x : v.w;
}

__global__ void __launch_bounds__(128) fused_kernel(
    const float* __restrict__ arc_w, const int* __restrict__ arc_to,
    const int*   __restrict__ arc_ilab,
    const int*   __restrict__ model_ids, const float* __restrict__ alpha,
    const int*   __restrict__ states,
    const int*   __restrict__ bo_to, const float* __restrict__ bo_w,
    const float* __restrict__ final_w, const int* __restrict__ eos_ptr,
    float* __restrict__ out_scores, float* __restrict__ out_next,
    int V, int per_model, int B, int S, int K)
{
    const int tile = blockIdx.x;
    const int m    = blockIdx.y;
    const int h0   = blockIdx.z * CHUNK;
    const int t    = threadIdx.x;
    const int vlo  = tile * TILE;

    __shared__ int   sh_h [CHUNK];
    __shared__ float sh_c [CHUNK];
    __shared__ float sh_fw[CHUNK];
    __shared__ int   sh_s0[CHUNK];
    __shared__ int   sh_nl[CHUNK];
    __shared__ int   sh_lb[CHUNK][MAXLVL];
    __shared__ float sh_la[CHUNK][MAXLVL];
    __shared__ unsigned char sh_slow[CHUNK];
    __shared__ int      sh_cnt[NCAP][4];
    __shared__ unsigned sh_pl [NCAP][4][BCAP];   // local | key<<10
    __shared__ float    sh_ps [NCAP][4][BCAP];   // score (alpha-scaled)
    __shared__ float    sh_pn [NCAP][4][BCAP];   // next state
    __shared__ int   sh_n;
    __shared__ int   sh_anyslow;

    if (t == 0) { sh_n = 0; sh_anyslow = 0; }
    if (t < NCAP * 4) ((int*)sh_cnt)[t] = 0;
    sh_slow[t] = 0;
    __syncthreads();

    const float a   = __ldg(alpha + m);
    const int   eos = __ldg(eos_ptr);

    // ---- Phase A: compact hyps + chain walk (one hyp per thread) ----
    {
        int h = h0 + t;
        if (h < B && __ldg(model_ids + h) == m) {
            int s = __ldg(states + h);
            const int s_first = s;
            float acc = 0.f;
            int nl = 0;
            int   lb[MAXLVL] = {0, 0, 0, 0};
            float la[MAXLVL] = {0.f, 0.f, 0.f, 0.f};
            #pragma unroll
            for (int i = 0; i < MAXLVL; i++) {
                int mm = s / S, r = s - mm * S;
                if (r == 0) break;             // reached start state
                lb[nl] = mm * per_model + V + (r - 1) * K;
                la[nl] = acc;
                nl++;
                acc += __ldg(bo_w + s);
                s = __ldg(bo_to + s);
            }
            int slot = atomicAdd(&sh_n, 1);
            sh_h [slot] = h;
            sh_c [slot] = acc * a;
            sh_s0[slot] = s_first;
            sh_fw[slot] = __ldg(final_w + s_first) * a;
            sh_nl[slot] = nl;
            #pragma unroll
            for (int l = 0; l < MAXLVL; l++) { sh_lb[slot][l] = lb[l]; sh_la[slot][l] = la[l]; }
            if (slot >= NCAP) { sh_slow[slot] = 1; sh_anyslow = 1; }
        }
    }

    // ---- Tile load (two float4/int4 per thread; overlaps Phase A) ----
    const long long base = (long long)m * per_model + (long long)vlo;
    const float4* wsrc = (const float4*)(arc_w  + base);
    const int4*   tsrc = (const int4*)  (arc_to + base);
    float4 w0 = __ldg(wsrc + t);
    float4 w1 = __ldg(wsrc + t + 128);
    int4   i0 = __ldg(tsrc + t);
    int4   i1 = __ldg(tsrc + t + 128);
    float4 n0 = make_float4((float)i0.x, (float)i0.y, (float)i0.z, (float)i0.w);
    float4 n1 = make_float4((float)i1.x, (float)i1.y, (float)i1.z, (float)i1.w);

    __syncthreads();

    const int n = sh_n;
    if (n == 0) return;

    const int warp = t >> 5;

    // ---- Phase A': build patch buckets, one (slot, level) per thread ----
    for (int idx = t; idx < n * MAXLVL; idx += CHUNK) {
        const int slot = idx >> 2, l = idx & 3;
        if (slot >= NCAP) continue;           // slow path covers it
        if (l >= sh_nl[slot]) continue;
        const int   lbase = sh_lb[slot][l];
        const float lacc  = sh_la[slot][l];
        int lo = 0, hi = K;                   // lower_bound(vlo)
        while (lo < hi) {
            int mid = (lo + hi) >> 1;
            if (__ldg(arc_ilab + lbase + mid) < vlo) lo = mid + 1; else hi = mid;
        }
        const int rlo = lo;
        hi = K;                               // lower_bound(vlo + TILE)
        while (lo < hi) {
            int mid = (lo + hi) >> 1;
            if (__ldg(arc_ilab + lbase + mid) < vlo + TILE) lo = mid + 1; else hi = mid;
        }
        const int rhi = lo;
        for (int j = rlo; j < rhi; j++) {
            const int il = __ldg(arc_ilab + lbase + j);
            if (il == eos) continue;          // eos column is fixed
            const int local = il - vlo;       // 0..1023
            const int wp = (local & 511) >> 7;
            int c = atomicAdd(&sh_cnt[slot][wp], 1);
            if (c < BCAP) {
                sh_pl[slot][wp][c] = (unsigned)local | ((unsigned)((l << 6) | j) << 10);
                sh_ps[slot][wp][c] = (lacc + __ldg(arc_w + lbase + j)) * a;
                sh_pn[slot][wp][c] = (float)__ldg(arc_to + lbase + j);
            } else {
                sh_slow[slot] = 1; sh_anyslow = 1;
            }
        }
    }
    __syncthreads();

    // ---- Phase A'': extract this thread's patches into registers ----
    int      np = 0;
    unsigned pmeta[PCAP];     // slot<<20 | key<<10 | local
    float    psv[PCAP], pnv[PCAP];
    {
        const int nn = (n < NCAP) ? n : NCAP;
        for (int slot = 0; slot < nn; slot++) {
            int cn = sh_cnt[slot][warp];
            if (cn > BCAP) cn = BCAP;
            for (int e = 0; e < cn; e++) {
                const unsigned pl = sh_pl[slot][warp][e];
                const int local = (int)(pl & 1023u);
                if (((local & 511) >> 2) != t) continue;    // not my slot
                const unsigned key = pl >> 10;              // <= 255
                const unsigned id  = ((unsigned)slot << 20) | (unsigned)local;
                bool dup = false;
                for (int k2 = 0; k2 < np; k2++) {
                    if ((pmeta[k2] & 0xFFF003FFu) == id) {  // same (slot,label)
                        dup = true;
                        if (key < ((pmeta[k2] >> 10) & 255u)) {   // better prio
                            pmeta[k2] = id | (key << 10);
                            psv[k2] = sh_ps[slot][warp][e];
                            pnv[k2] = sh_pn[slot][warp][e];
                        }
                        break;
                    }
                }
                if (!dup) {
                    if (np < PCAP) {
                        pmeta[np] = id | (key << 10);
                        psv[np] = sh_ps[slot][warp][e];
                        pnv[np] = sh_pn[slot][warp][e];
                        np++;
                    } else { sh_slow[slot] = 1; sh_anyslow = 1; }
                }
            }
        }
    }
    __syncthreads();    // make sh_anyslow/sh_slow uniform for the slow pass

    // ---- Store loop: defaults in registers, single-compare patch gate ----
    const bool eos_in   = (unsigned)(eos - vlo) < (unsigned)TILE;
    const int  eos_loc  = eos - vlo;
    const bool eos_mine = eos_in && (((eos_loc & 511) >> 2) == t);
    const int  eos_comp = eos_loc & 3;

    int pp = 0;
    int next_slot = np ? (int)(pmeta[0] >> 20) : -1;

    for (int i = 0; i < n; i++) {
        const float c = sh_c[i];
        float4 s0, s1;
        s0.x = fmaf(a, w0.x, c); s0.y = fmaf(a, w0.y, c);
        s0.z = fmaf(a, w0.z, c); s0.w = fmaf(a, w0.w, c);
        s1.x = fmaf(a, w1.x, c); s1.y = fmaf(a, w1.y, c);
        s1.z = fmaf(a, w1.z, c); s1.w = fmaf(a, w1.w, c);
        float4 nx0 = n0, nx1 = n1;

        if (i == next_slot) {                               // rare
            do {
                const unsigned mt = pmeta[pp];
                const int local = (int)(mt & 1023u);
                const int comp  = local & 3;
                const float sv = psv[pp], nv = pnv[pp];
                if (local < 512) { setc(s0, comp, sv); setc(nx0, comp, nv); }
                else             { setc(s1, comp, sv); setc(nx1, comp, nv); }
                pp++;
            } while (pp < np && (int)(pmeta[pp] >> 20) == i);
            next_slot = (pp < np) ? (int)(pmeta[pp] >> 20) : -1;
        }
        if (eos_mine) {                                     // eos wins all
            const float sv = sh_fw[i];
            const float nv = (float)sh_s0[i];
            if (eos_loc < 512) { setc(s0, eos_comp, sv); setc(nx0, eos_comp, nv); }
            else               { setc(s1, eos_comp, sv); setc(nx1, eos_comp, nv); }
        }

        const long long off = (long long)sh_h[i] * V + (long long)vlo;
        float4* sdst = (float4*)(out_scores + off);
        __stcs(sdst + t,       s0);
        __stcs(sdst + t + 128, s1);
        if (out_next) {
            float4* ndst = (float4*)(out_next + off);
            __stcs(ndst + t,       nx0);
            __stcs(ndst + t + 128, nx1);
        }
    }

    // ---- Rare fallback: full-priority gmem patch for slow slots ----
    if (sh_anyslow) {
        __syncthreads();     // order default stores before patch overwrites
        for (int slot = 0; slot < n; slot++) {
            if (!sh_slow[slot]) continue;
            const int nl = sh_nl[slot];
            const long long off = (long long)sh_h[slot] * V;
            for (int idx = t; idx < nl * K; idx += CHUNK) {
                const int l = idx / K, j = idx - l * K;
                const int lbase = sh_lb[slot][l];
                const int il = __ldg(arc_ilab + lbase + j);
                if (il < vlo || il >= vlo + TILE) continue;
                if (il == eos) continue;
                if (j > 0 && __ldg(arc_ilab + lbase + j - 1) == il) continue;
                bool shadowed = false;
                for (int l2 = 0; l2 < l; l2++) {
                    const int b2 = sh_lb[slot][l2];
                    int lo = 0, hi = K;
                    while (lo < hi) {
                        int mid = (lo + hi) >> 1;
                        if (__ldg(arc_ilab + b2 + mid) < il) lo = mid + 1; else hi = mid;
                    }
                    if (lo < K && __ldg(arc_ilab + b2 + lo) == il) { shadowed = true; break; }
                }
                if (shadowed) continue;
                out_scores[off + il] = (sh_la[slot][l] + __ldg(arc_w + lbase + j)) * a;
                if (out_next) out_next[off + il] = (float)__ldg(arc_to + lbase + j);
            }
        }
    }
}

// ---------------- fallback: monolithic kernel (odd shapes) ----------------
#define MAXK 64
__global__ void advance_kernel(
    const float* __restrict__ arc_w, const int* __restrict__ arc_to,
    const int* __restrict__ arc_ilab,
    const int* __restrict__ bo_to, const float* __restrict__ bo_w,
    const float* __restrict__ final_w, const float* __restrict__ alpha,
    const int* __restrict__ states, const int* __restrict__ model_ids,
    const int* __restrict__ eos_ptr,
    float* __restrict__ out_scores, float* __restrict__ out_next,
    int V, int S, int K)
{
    __shared__ int       sh_ilab[MAXLVL * MAXK];
    __shared__ float     sh_w   [MAXLVL * MAXK];
    __shared__ int       sh_to  [MAXLVL * MAXK];
    __shared__ long long sh_level_base[MAXLVL];
    __shared__ float     sh_level_acc [MAXLVL];
    __shared__ int       sh_nl;
    __shared__ long long sh_start_base;
    __shared__ float     sh_start_acc;

    const int b = blockIdx.x;
    if (threadIdx.x == 0) {
        int s = states[b];
        float acc = 0.f;
        int nl = 0;
        long long start_base = -1;
        float start_acc = 0.f;
        const long long per_model = (long long)V + (long long)(S - 1) * K;
        #pragma unroll
        for (int i = 0; i < MAXLVL; i++) {
            int m = s / S, r = s - m * S;
            if (r == 0) { start_base = (long long)m * per_model; start_acc = acc; break; }
            sh_level_base[nl] = (long long)m * per_model + V + (long long)(r - 1) * K;
            sh_level_acc [nl] = acc;
            nl++;
            acc += bo_w[s];
            s = bo_to[s];
        }
        sh_nl = nl; sh_start_base = start_base; sh_start_acc = start_acc;
    }
    __syncthreads();

    const int nl = sh_nl;
    for (int idx = threadIdx.x; idx < nl * K; idx += blockDim.x) {
        int l = idx / K, j = idx - l * K;
        long long base = sh_level_base[l];
        sh_ilab[l * MAXK + j] = arc_ilab[base + j];
        sh_w   [l * MAXK + j] = arc_w   [base + j];
        sh_to  [l * MAXK + j] = arc_to  [base + j];
    }

    const int       s0      = states[b];
    const float     alpha_b = alpha[model_ids[b]];
    const int       eos     = eos_ptr[0];
    const long long sb      = sh_start_base;
    const float     sa      = sh_start_acc;
    const float     eos_sc  = final_w[s0] * alpha_b;
    const long long off     = (long long)b * V;

    for (int v = threadIdx.x; v < V; v += blockDim.x) {
        float sc = 0.f, nx = 0.f;
        if (sb >= 0) {
            sc = (sa + arc_w[sb + v]) * alpha_b;
            nx = (float)arc_to[sb + v];
        }
        if (v == eos) { sc = eos_sc; nx = (float)s0; }
        out_scores[off + v] = sc;
        if (out_next) out_next[off + v] = nx;
    }
    __syncthreads();

    for (int idx = threadIdx.x; idx < nl * K; idx += blockDim.x) {
        int l = idx / K, j = idx - l * K;
        int il = sh_ilab[l * MAXK + j];
        if (il == eos) continue;
        if (j > 0 && sh_ilab[l * MAXK + j - 1] == il) continue;
        bool shadowed = false;
        for (int l2 = 0; l2 < l; l2++) {
            const int* arr = sh_ilab + l2 * MAXK;
            int lo = 0, hi = K;
            while (lo < hi) { int mid = (lo + hi) >> 1; if (arr[mid] < il) lo = mid + 1; else hi = mid; }
            if (lo < K && arr[lo] == il) { shadowed = true; break; }
        }
        if (shadowed) continue;
        out_scores[off + il] = (sh_level_acc[l] + sh_w[l * MAXK + j]) * alpha_b;
        if (out_next) out_next[off + il] = (float)sh_to[l * MAXK + j];
    }
}

extern "C" void kernel_launch(void* const* d_in, const int* in_sizes, int n_in,
                              void* d_out, int out_size)
{
    const float* arc_w     = (const float*)d_in[0];
    const int*   arc_to    = (const int*)  d_in[1];
    const int*   arc_ilab  = (const int*)  d_in[3];
    const int*   bo_to     = (const int*)  d_in[4];
    const float* bo_w      = (const float*)d_in[5];
    const float* final_w   = (const float*)d_in[6];
    const float* alpha     = (const float*)d_in[7];
    const int*   states    = (const int*)  d_in[8];
    const int*   model_ids = (const int*)  d_in[9];
    const int*   eos       = (const int*)  d_in[10];

    const long long A        = in_sizes[0];
    const long long n_states = in_sizes[4];
    const long long M        = in_sizes[7];
    const long long B        = in_sizes[8];
    const long long S        = n_states / M;

    long long V = (long long)out_size / (2 * B);
    bool write_next = true;
    if (V * 2 * B != (long long)out_size) {
        V = (long long)out_size / B;
        write_next = false;
    }
    const long long per_model = A / M;
    const int K = (int)((per_model - V) / (S - 1));

    float* out_scores = (float*)d_out;
    float* out_next   = write_next ? out_scores + B * V : nullptr;

    if ((V % TILE) == 0 && K <= 64) {   // key packing needs j < 64
        dim3 grid((unsigned)(V / TILE), (unsigned)M, (unsigned)((B + CHUNK - 1) / CHUNK));
        fused_kernel<<<grid, CHUNK>>>(
            arc_w, arc_to, arc_ilab, model_ids, alpha, states, bo_to, bo_w,
            final_w, eos,
            out_scores, out_next, (int)V, (int)per_model, (int)B, (int)S, K);
    } else {
        advance_kernel<<<(unsigned)B, 256>>>(
            arc_w, arc_to, arc_ilab, bo_to, bo_w, final_w, alpha,
            states, model_ids, eos,
            out_scores, out_next, (int)V, (int)S, K);
    }
}

// round 14
// speedup vs baseline: 1.5221x; 1.5221x over previous
#include <cuda_runtime.h>

// GPUBiasingMultiModel R14: EXACTLY R10 (best: 34.3us) + per-(hyp,warp) owner
// lane masks gating the patch scan. One-variable experiment: R11 bundled this
// mask with TILE=512 (the regression cause per R12's isolation); R13's
// register hoist spilled. This applies the mask to the unmodified R10 shape.

#define MAXLVL 4
#define TILE   1024   // labels per tile (8 floats/thread @128 thr)
#define CHUNK  128    // hyp indices per block (== blockDim)
#define NCAP   32     // hyp slots with fast-path buckets
#define BCAP   8      // entries per (hyp, warp) bucket

__device__ __forceinline__ void setc(float4& v, int c, float x) {
    v.x = (c == 0) ? x : v.x;
    v.y = (c == 1) ? x : v.y;
    v.z = (c == 2) ? x : v.z;
    v.w = (c == 3) ? x : v.w;
}

__global__ void __launch_bounds__(128) fused_kernel(
    const float* __restrict__ arc_w, const int* __restrict__ arc_to,
    const int*   __restrict__ arc_ilab,
    const int*   __restrict__ model_ids, const float* __restrict__ alpha,
    const int*   __restrict__ states,
    const int*   __restrict__ bo_to, const float* __restrict__ bo_w,
    const float* __restrict__ final_w, const int* __restrict__ eos_ptr,
    float* __restrict__ out_scores, float* __restrict__ out_next,
    int V, int per_model, int B, int S, int K)
{
    const int tile = blockIdx.x;
    const int m    = blockIdx.y;
    const int h0   = blockIdx.z * CHUNK;
    const int t    = threadIdx.x;
    const int vlo  = tile * TILE;

    __shared__ int   sh_h [CHUNK];
    __shared__ float sh_c [CHUNK];
    __shared__ float sh_fw[CHUNK];
    __shared__ int   sh_s0[CHUNK];
    __shared__ int   sh_nl[CHUNK];
    __shared__ int   sh_lb[CHUNK][MAXLVL];
    __shared__ float sh_la[CHUNK][MAXLVL];
    __shared__ unsigned char sh_slow[CHUNK];
    __shared__ int      sh_cnt  [NCAP][4];
    __shared__ unsigned sh_pmask[NCAP][4];       // owner lanes per warp
    __shared__ unsigned sh_pl [NCAP][4][BCAP];   // local | key<<10
    __shared__ float    sh_ps [NCAP][4][BCAP];   // score (alpha-scaled)
    __shared__ float    sh_pn [NCAP][4][BCAP];   // next state
    __shared__ int   sh_n;
    __shared__ int   sh_anyslow;

    if (t == 0) { sh_n = 0; sh_anyslow = 0; }
    if (t < NCAP * 4) { ((int*)sh_cnt)[t] = 0; ((unsigned*)sh_pmask)[t] = 0u; }
    sh_slow[t] = 0;
    __syncthreads();

    const float a   = __ldg(alpha + m);
    const int   eos = __ldg(eos_ptr);

    // ---- Phase A: compact hyps + chain walk (one hyp per thread) ----
    {
        int h = h0 + t;
        if (h < B && __ldg(model_ids + h) == m) {
            int s = __ldg(states + h);
            const int s_first = s;
            float acc = 0.f;
            int nl = 0;
            int   lb[MAXLVL] = {0, 0, 0, 0};
            float la[MAXLVL] = {0.f, 0.f, 0.f, 0.f};
            #pragma unroll
            for (int i = 0; i < MAXLVL; i++) {
                int mm = s / S, r = s - mm * S;
                if (r == 0) break;             // reached start state
                lb[nl] = mm * per_model + V + (r - 1) * K;
                la[nl] = acc;
                nl++;
                acc += __ldg(bo_w + s);
                s = __ldg(bo_to + s);
            }
            int slot = atomicAdd(&sh_n, 1);
            sh_h [slot] = h;
            sh_c [slot] = acc * a;
            sh_s0[slot] = s_first;
            sh_fw[slot] = __ldg(final_w + s_first) * a;
            sh_nl[slot] = nl;
            #pragma unroll
            for (int l = 0; l < MAXLVL; l++) { sh_lb[slot][l] = lb[l]; sh_la[slot][l] = la[l]; }
            if (slot >= NCAP) { sh_slow[slot] = 1; sh_anyslow = 1; }
        }
    }

    // ---- Tile load (independent; overlaps Phase A latency) ----
    const long long base = (long long)m * per_model + (long long)vlo;
    const float4* wsrc = (const float4*)(arc_w  + base);
    const int4*   tsrc = (const int4*)  (arc_to + base);
    float4 w0 = __ldg(wsrc + t);
    float4 w1 = __ldg(wsrc + t + 128);
    int4   i0 = __ldg(tsrc + t);
    int4   i1 = __ldg(tsrc + t + 128);
    float4 n0 = make_float4((float)i0.x, (float)i0.y, (float)i0.z, (float)i0.w);
    float4 n1 = make_float4((float)i1.x, (float)i1.y, (float)i1.z, (float)i1.w);

    __syncthreads();

    const int n = sh_n;
    if (n == 0) return;

    // ---- Phase A': build patch buckets + owner masks ----
    for (int idx = t; idx < n * MAXLVL; idx += CHUNK) {
        const int slot = idx >> 2, l = idx & 3;
        if (slot >= NCAP) continue;           // slow path covers it
        if (l >= sh_nl[slot]) continue;
        const int   lbase = sh_lb[slot][l];
        const float lacc  = sh_la[slot][l];
        int lo = 0, hi = K;                   // lower_bound(vlo)
        while (lo < hi) {
            int mid = (lo + hi) >> 1;
            if (__ldg(arc_ilab + lbase + mid) < vlo) lo = mid + 1; else hi = mid;
        }
        const int rlo = lo;
        hi = K;                               // lower_bound(vlo + TILE)
        while (lo < hi) {
            int mid = (lo + hi) >> 1;
            if (__ldg(arc_ilab + lbase + mid) < vlo + TILE) lo = mid + 1; else hi = mid;
        }
        const int rhi = lo;
        for (int j = rlo; j < rhi; j++) {
            const int il = __ldg(arc_ilab + lbase + j);
            if (il == eos) continue;          // eos column is fixed
            const int local = il - vlo;
            const int w = (local & 511) >> 7; // owning warp
            int c = atomicAdd(&sh_cnt[slot][w], 1);
            if (c < BCAP) {
                sh_pl[slot][w][c] = (unsigned)local | ((unsigned)((l << 6) | j) << 10);
                sh_ps[slot][w][c] = (lacc + __ldg(arc_w + lbase + j)) * a;
                sh_pn[slot][w][c] = (float)__ldg(arc_to + lbase + j);
                atomicOr(&sh_pmask[slot][w], 1u << ((local >> 2) & 31));
            } else {
                sh_slow[slot] = 1; sh_anyslow = 1;
            }
        }
    }
    __syncthreads();

    // ---- Store loop: defaults in registers, mask-gated patch scan ----
    const bool eos_in  = (unsigned)(eos - vlo) < (unsigned)TILE;
    const int  eos_loc = eos - vlo;
    const int  warp    = t >> 5;
    const int  lanebit = t & 31;

    for (int i = 0; i < n; i++) {
        const float c = sh_c[i];
        float4 s0, s1;
        s0.x = fmaf(a, w0.x, c); s0.y = fmaf(a, w0.y, c);
        s0.z = fmaf(a, w0.z, c); s0.w = fmaf(a, w0.w, c);
        s1.x = fmaf(a, w1.x, c); s1.y = fmaf(a, w1.y, c);
        s1.z = fmaf(a, w1.z, c); s1.w = fmaf(a, w1.w, c);
        float4 nx0 = n0, nx1 = n1;

        if (i < NCAP && ((sh_pmask[i][warp] >> lanebit) & 1u)) {
            int cn = sh_cnt[i][warp];
            if (cn > BCAP) cn = BCAP;
            unsigned bk0 = 0xFFFFFFFFu, bk1 = 0xFFFFFFFFu;  // best key/slot
            for (int e = 0; e < cn; e++) {
                const unsigned pl = sh_pl[i][warp][e];      // broadcast
                const int local = (int)(pl & 1023u);
                if (((local & 511) >> 2) != t) continue;    // not my slot
                const unsigned key = pl >> 10;
                const int half = local >> 9;
                const int comp = local & 3;
                const int sh8  = comp * 8;
                const unsigned cur = ((half ? bk1 : bk0) >> sh8) & 255u;
                if (key < cur) {                            // better priority
                    const float sv = sh_ps[i][warp][e];
                    const float nv = sh_pn[i][warp][e];
                    if (!half) {
                        setc(s0, comp, sv); setc(nx0, comp, nv);
                        bk0 = (bk0 & ~(255u << sh8)) | (key << sh8);
                    } else {
                        setc(s1, comp, sv); setc(nx1, comp, nv);
                        bk1 = (bk1 & ~(255u << sh8)) | (key << sh8);
                    }
                }
            }
        }
        if (eos_in && ((eos_loc & 511) >> 2) == t) {        // eos wins all
            const int comp = eos_loc & 3;
            const float sv = sh_fw[i];
            const float nv = (float)sh_s0[i];
            if (eos_loc < 512) { setc(s0, comp, sv); setc(nx0, comp, nv); }
            else               { setc(s1, comp, sv); setc(nx1, comp, nv); }
        }

        const long long off = (long long)sh_h[i] * V + (long long)vlo;
        float4* sdst = (float4*)(out_scores + off);
        __stcs(sdst + t,       s0);
        __stcs(sdst + t + 128, s1);
        if (out_next) {
            float4* ndst = (float4*)(out_next + off);
            __stcs(ndst + t,       nx0);
            __stcs(ndst + t + 128, nx1);
        }
    }

    // ---- Rare fallback: full-priority gmem patch for slow slots ----
    if (sh_anyslow) {
        __syncthreads();     // order default stores before patch overwrites
        for (int slot = 0; slot < n; slot++) {
            if (!sh_slow[slot]) continue;
            const int nl = sh_nl[slot];
            const long long off = (long long)sh_h[slot] * V;
            for (int idx = t; idx < nl * K; idx += CHUNK) {
                const int l = idx / K, j = idx - l * K;
                const int lbase = sh_lb[slot][l];
                const int il = __ldg(arc_ilab + lbase + j);
                if (il < vlo || il >= vlo + TILE) continue;
                if (il == eos) continue;
                if (j > 0 && __ldg(arc_ilab + lbase + j - 1) == il) continue;
                bool shadowed = false;
                for (int l2 = 0; l2 < l; l2++) {
                    const int b2 = sh_lb[slot][l2];
                    int lo = 0, hi = K;
                    while (lo < hi) {
                        int mid = (lo + hi) >> 1;
                        if (__ldg(arc_ilab + b2 + mid) < il) lo = mid + 1; else hi = mid;
                    }
                    if (lo < K && __ldg(arc_ilab + b2 + lo) == il) { shadowed = true; break; }
                }
                if (shadowed) continue;
                out_scores[off + il] = (sh_la[slot][l] + __ldg(arc_w + lbase + j)) * a;
                if (out_next) out_next[off + il] = (float)__ldg(arc_to + lbase + j);
            }
        }
    }
}

// ---------------- fallback: monolithic kernel (odd shapes) ----------------
#define MAXK 64
__global__ void advance_kernel(
    const float* __restrict__ arc_w, const int* __restrict__ arc_to,
    const int* __restrict__ arc_ilab,
    const int* __restrict__ bo_to, const float* __restrict__ bo_w,
    const float* __restrict__ final_w, const float* __restrict__ alpha,
    const int* __restrict__ states, const int* __restrict__ model_ids,
    const int* __restrict__ eos_ptr,
    float* __restrict__ out_scores, float* __restrict__ out_next,
    int V, int S, int K)
{
    __shared__ int       sh_ilab[MAXLVL * MAXK];
    __shared__ float     sh_w   [MAXLVL * MAXK];
    __shared__ int       sh_to  [MAXLVL * MAXK];
    __shared__ long long sh_level_base[MAXLVL];
    __shared__ float     sh_level_acc [MAXLVL];
    __shared__ int       sh_nl;
    __shared__ long long sh_start_base;
    __shared__ float     sh_start_acc;

    const int b = blockIdx.x;
    if (threadIdx.x == 0) {
        int s = states[b];
        float acc = 0.f;
        int nl = 0;
        long long start_base = -1;
        float start_acc = 0.f;
        const long long per_model = (long long)V + (long long)(S - 1) * K;
        #pragma unroll
        for (int i = 0; i < MAXLVL; i++) {
            int m = s / S, r = s - m * S;
            if (r == 0) { start_base = (long long)m * per_model; start_acc = acc; break; }
            sh_level_base[nl] = (long long)m * per_model + V + (long long)(r - 1) * K;
            sh_level_acc [nl] = acc;
            nl++;
            acc += bo_w[s];
            s = bo_to[s];
        }
        sh_nl = nl; sh_start_base = start_base; sh_start_acc = start_acc;
    }
    __syncthreads();

    const int nl = sh_nl;
    for (int idx = threadIdx.x; idx < nl * K; idx += blockDim.x) {
        int l = idx / K, j = idx - l * K;
        long long base = sh_level_base[l];
        sh_ilab[l * MAXK + j] = arc_ilab[base + j];
        sh_w   [l * MAXK + j] = arc_w   [base + j];
        sh_to  [l * MAXK + j] = arc_to  [base + j];
    }

    const int       s0      = states[b];
    const float     alpha_b = alpha[model_ids[b]];
    const int       eos     = eos_ptr[0];
    const long long sb      = sh_start_base;
    const float     sa      = sh_start_acc;
    const float     eos_sc  = final_w[s0] * alpha_b;
    const long long off     = (long long)b * V;

    for (int v = threadIdx.x; v < V; v += blockDim.x) {
        float sc = 0.f, nx = 0.f;
        if (sb >= 0) {
            sc = (sa + arc_w[sb + v]) * alpha_b;
            nx = (float)arc_to[sb + v];
        }
        if (v == eos) { sc = eos_sc; nx = (float)s0; }
        out_scores[off + v] = sc;
        if (out_next) out_next[off + v] = nx;
    }
    __syncthreads();

    for (int idx = threadIdx.x; idx < nl * K; idx += blockDim.x) {
        int l = idx / K, j = idx - l * K;
        int il = sh_ilab[l * MAXK + j];
        if (il == eos) continue;
        if (j > 0 && sh_ilab[l * MAXK + j - 1] == il) continue;
        bool shadowed = false;
        for (int l2 = 0; l2 < l; l2++) {
            const int* arr = sh_ilab + l2 * MAXK;
            int lo = 0, hi = K;
            while (lo < hi) { int mid = (lo + hi) >> 1; if (arr[mid] < il) lo = mid + 1; else hi = mid; }
            if (lo < K && arr[lo] == il) { shadowed = true; break; }
        }
        if (shadowed) continue;
        out_scores[off + il] = (sh_level_acc[l] + sh_w[l * MAXK + j]) * alpha_b;
        if (out_next) out_next[off + il] = (float)sh_to[l * MAXK + j];
    }
}

extern "C" void kernel_launch(void* const* d_in, const int* in_sizes, int n_in,
                              void* d_out, int out_size)
{
    const float* arc_w     = (const float*)d_in[0];
    const int*   arc_to    = (const int*)  d_in[1];
    const int*   arc_ilab  = (const int*)  d_in[3];
    const int*   bo_to     = (const int*)  d_in[4];
    const float* bo_w      = (const float*)d_in[5];
    const float* final_w   = (const float*)d_in[6];
    const float* alpha     = (const float*)d_in[7];
    const int*   states    = (const int*)  d_in[8];
    const int*   model_ids = (const int*)  d_in[9];
    const int*   eos       = (const int*)  d_in[10];

    const long long A        = in_sizes[0];
    const long long n_states = in_sizes[4];
    const long long M        = in_sizes[7];
    const long long B        = in_sizes[8];
    const long long S        = n_states / M;

    long long V = (long long)out_size / (2 * B);
    bool write_next = true;
    if (V * 2 * B != (long long)out_size) {
        V = (long long)out_size / B;
        write_next = false;
    }
    const long long per_model = A / M;
    const int K = (int)((per_model - V) / (S - 1));

    float* out_scores = (float*)d_out;
    float* out_next   = write_next ? out_scores + B * V : nullptr;

    if ((V % TILE) == 0 && K <= 64) {   // key packing needs j < 64
        dim3 grid((unsigned)(V / TILE), (unsigned)M, (unsigned)((B + CHUNK - 1) / CHUNK));
        fused_kernel<<<grid, CHUNK>>>(
            arc_w, arc_to, arc_ilab, model_ids, alpha, states, bo_to, bo_w,
            final_w, eos,
            out_scores, out_next, (int)V, (int)per_model, (int)B, (int)S, K);
    } else {
        advance_kernel<<<(unsigned)B, 256>>>(
            arc_w, arc_to, arc_ilab, bo_to, bo_w, final_w, alpha,
            states, model_ids, eos,
            out_scores, out_next, (int)V, (int)S, K);
    }
}